// round 6
// baseline (speedup 1.0000x reference)
#include <cuda_runtime.h>
#include <cstdint>

// DepthToSpace (DCR, block=2): in [16,256,128,128] f32 -> out [16,64,256,256] f32
// out[b, c, 2h+j, 2w+r] = in[b, (2j+r)*64 + c, h, w]
//
// One thread-iteration per 8 consecutive output floats. For a fixed output
// row, elements interleave two contiguous input rows d0 = 2j*64 + c and
// d1 = d0 + 64:
//   out[8q + 2k]   = in[d0][4q + k]
//   out[8q + 2k+1] = in[d1][4q + k]     k = 0..3
// => two coalesced 16B non-coherent loads + ONE contiguous 32B streaming
//    store (st.global.cs.v8.f32) per iteration. Warp store footprint: 1024B
//    contiguous, fully written. Warp load footprint per LDG: 512B contiguous.
// Neither stream has reuse -> evict-first (.cs) on the stores keeps L2 from
// holding dead write lines.

static constexpr unsigned B  = 16;
static constexpr unsigned D  = 256;   // input channels
static constexpr unsigned C  = 64;    // output channels
static constexpr unsigned H  = 128;
static constexpr unsigned W  = 128;
static constexpr unsigned OH = 256;
static constexpr unsigned OW = 256;

static constexpr unsigned OW8 = OW / 8;                     // 32 chunks per out row
static constexpr unsigned TOTAL_F8 = B * C * OH * OW8;      // 8,388,608 iterations
static constexpr unsigned D_STRIDE_F4 = H * W / 4;          // 4096 float4 per input channel
static constexpr unsigned D1_OFF_F4   = C * D_STRIDE_F4;    // +64 channels, float4 units

static constexpr unsigned NBLOCKS  = 4096;
static constexpr unsigned NTHREADS = 256;
static constexpr unsigned STRIDE   = NBLOCKS * NTHREADS;    // 1,048,576
static constexpr unsigned NITERS   = TOTAL_F8 / STRIDE;     // exactly 8

__global__ void __launch_bounds__(NTHREADS) d2s_kernel(const float4* __restrict__ in,
                                                       float* __restrict__ out) {
    const unsigned idx0 = blockIdx.x * NTHREADS + threadIdx.x;

#pragma unroll 4
    for (unsigned it = 0; it < NITERS; ++it) {
        unsigned idx = idx0 + it * STRIDE;

        unsigned q  = idx & (OW8 - 1);    // which 8-float chunk in the output row
        unsigned t  = idx >> 5;           // /OW8
        unsigned oh = t & (OH - 1);
        t >>= 8;                          // /OH
        unsigned c  = t & (C - 1);
        unsigned b  = t >> 6;             // /C

        unsigned h  = oh >> 1;
        unsigned j  = oh & 1;
        unsigned d0 = (j << 7) + c;       // (2j)*64 + c

        // float4 index of in[b][d0][h][4q]
        unsigned i0 = (b * D + d0) * D_STRIDE_F4 + h * (W / 4) + q;

        float4 a  = __ldg(&in[i0]);
        float4 bb = __ldg(&in[i0 + D1_OFF_F4]);

        // One 256-bit streaming store: out floats [8*idx .. 8*idx+7].
        float* op = out + 8ull * idx;
        asm volatile(
            "st.global.cs.v8.f32 [%0], {%1, %2, %3, %4, %5, %6, %7, %8};"
            :: "l"(op),
               "f"(a.x), "f"(bb.x), "f"(a.y), "f"(bb.y),
               "f"(a.z), "f"(bb.z), "f"(a.w), "f"(bb.w)
            : "memory");
    }
}

extern "C" void kernel_launch(void* const* d_in, const int* in_sizes, int n_in,
                              void* d_out, int out_size) {
    (void)in_sizes; (void)n_in; (void)out_size;
    const float4* in = (const float4*)d_in[0];
    float* out = (float*)d_out;
    d2s_kernel<<<NBLOCKS, NTHREADS>>>(in, out);
}

// round 7
// speedup vs baseline: 1.0155x; 1.0155x over previous
#include <cuda_runtime.h>
#include <cstdint>

// DepthToSpace (DCR, block=2): in [16,256,128,128] f32 -> out [16,64,256,256] f32
// out[b, c, 2h+j, 2w+r] = in[b, (2j+r)*64 + c, h, w]
//
// One thread-iteration per 8 consecutive output floats. For a fixed output
// row, elements interleave two contiguous input rows d0 = 2j*64 + c and
// d1 = d0 + 64:
//   out[8q + 2k]   = in[d0][4q + k]
//   out[8q + 2k+1] = in[d1][4q + k]     k = 0..3
// => two coalesced 16B non-coherent loads + ONE contiguous 32B store
//    (st.global.v8.f32, sm_100+) per iteration. Warp store footprint per STG:
//    1024B contiguous fully written; warp load footprint per LDG: 512B.
//
// 8192 CTAs x 4 fully-unrolled iterations: finer CTA granularity halves the
// per-SM CTA-count quantization tail vs 4096x8, and the unrolled body lets
// ptxas front-batch all 8 LDG.128 (MLP=8) ahead of the 4 stores.

static constexpr unsigned B  = 16;
static constexpr unsigned D  = 256;   // input channels
static constexpr unsigned C  = 64;    // output channels
static constexpr unsigned H  = 128;
static constexpr unsigned W  = 128;
static constexpr unsigned OH = 256;
static constexpr unsigned OW = 256;

static constexpr unsigned OW8 = OW / 8;                     // 32 chunks per out row
static constexpr unsigned TOTAL_F8 = B * C * OH * OW8;      // 8,388,608 iterations
static constexpr unsigned D_STRIDE_F4 = H * W / 4;          // 4096 float4 per input channel
static constexpr unsigned D1_OFF_F4   = C * D_STRIDE_F4;    // +64 channels, float4 units

static constexpr unsigned NBLOCKS  = 8192;
static constexpr unsigned NTHREADS = 256;
static constexpr unsigned STRIDE   = NBLOCKS * NTHREADS;    // 2,097,152
static constexpr unsigned NITERS   = TOTAL_F8 / STRIDE;     // exactly 4

__global__ void __launch_bounds__(NTHREADS) d2s_kernel(const float4* __restrict__ in,
                                                       float* __restrict__ out) {
    const unsigned idx0 = blockIdx.x * NTHREADS + threadIdx.x;

    float4 a[NITERS], bb[NITERS];

    // Phase 1: all loads (MLP = 2*NITERS outstanding LDG.128)
#pragma unroll
    for (unsigned it = 0; it < NITERS; ++it) {
        unsigned idx = idx0 + it * STRIDE;

        unsigned q  = idx & (OW8 - 1);    // which 8-float chunk in the output row
        unsigned t  = idx >> 5;           // /OW8
        unsigned oh = t & (OH - 1);
        t >>= 8;                          // /OH
        unsigned c  = t & (C - 1);
        unsigned b  = t >> 6;             // /C

        unsigned h  = oh >> 1;
        unsigned j  = oh & 1;
        unsigned d0 = (j << 7) + c;       // (2j)*64 + c

        // float4 index of in[b][d0][h][4q]
        unsigned i0 = (b * D + d0) * D_STRIDE_F4 + h * (W / 4) + q;

        a[it]  = __ldg(&in[i0]);
        bb[it] = __ldg(&in[i0 + D1_OFF_F4]);
    }

    // Phase 2: all stores (one 256-bit contiguous store per iteration)
#pragma unroll
    for (unsigned it = 0; it < NITERS; ++it) {
        unsigned idx = idx0 + it * STRIDE;
        float* op = out + 8ull * idx;
        asm volatile(
            "st.global.v8.f32 [%0], {%1, %2, %3, %4, %5, %6, %7, %8};"
            :: "l"(op),
               "f"(a[it].x), "f"(bb[it].x), "f"(a[it].y), "f"(bb[it].y),
               "f"(a[it].z), "f"(bb[it].z), "f"(a[it].w), "f"(bb[it].w)
            : "memory");
    }
}

extern "C" void kernel_launch(void* const* d_in, const int* in_sizes, int n_in,
                              void* d_out, int out_size) {
    (void)in_sizes; (void)n_in; (void)out_size;
    const float4* in = (const float4*)d_in[0];
    float* out = (float*)d_out;
    d2s_kernel<<<NBLOCKS, NTHREADS>>>(in, out);
}

// round 8
// speedup vs baseline: 1.0246x; 1.0090x over previous
#include <cuda_runtime.h>
#include <cstdint>

// DepthToSpace (DCR, block=2): in [16,256,128,128] f32 -> out [16,64,256,256] f32
// out[b, c, 2h+j, 2w+r] = in[b, (2j+r)*64 + c, h, w]
//
// One thread-iteration per 8 consecutive output floats. For a fixed output
// row, elements interleave two contiguous input rows d0 = 2j*64 + c and
// d1 = d0 + 64:
//   out[8q + 2k]   = in[d0][4q + k]
//   out[8q + 2k+1] = in[d1][4q + k]     k = 0..3
// => two coalesced 16B non-coherent loads + ONE contiguous 32B store
//    (st.global.v8.f32, sm_100+) per iteration. Warp store footprint per STG:
//    1024B contiguous fully written; warp load footprint per LDG: 512B.
//
// 16384 CTAs x 2 iterations: minimal per-SM CTA-count quantization tail.
// STRIDE = 2^22 touches only the b-field of the index decomposition, so the
// q/oh/c/h/j decomposition is loop-invariant: decompose once, second
// iteration's addresses are compile-time-constant offsets.

static constexpr unsigned B  = 16;
static constexpr unsigned D  = 256;   // input channels
static constexpr unsigned C  = 64;    // output channels
static constexpr unsigned H  = 128;
static constexpr unsigned W  = 128;
static constexpr unsigned OH = 256;
static constexpr unsigned OW = 256;

static constexpr unsigned OW8 = OW / 8;                     // 32 chunks per out row
static constexpr unsigned TOTAL_F8 = B * C * OH * OW8;      // 8,388,608 chunks
static constexpr unsigned D_STRIDE_F4 = H * W / 4;          // 4096 float4 per input channel
static constexpr unsigned D1_OFF_F4   = C * D_STRIDE_F4;    // +64 channels, float4 units

static constexpr unsigned NBLOCKS  = 16384;
static constexpr unsigned NTHREADS = 256;
static constexpr unsigned STRIDE   = NBLOCKS * NTHREADS;    // 4,194,304 = 2^22
static constexpr unsigned NITERS   = TOTAL_F8 / STRIDE;     // exactly 2

// Between iterations only b increases by STRIDE / (OW8*OH*C) = 8:
static constexpr unsigned I0_STEP_F4  = 8u * D * D_STRIDE_F4;  // 8,388,608 float4
static constexpr unsigned OUT_STEP_F1 = 8u * STRIDE;           // floats

__global__ void __launch_bounds__(NTHREADS) d2s_kernel(const float4* __restrict__ in,
                                                       float* __restrict__ out) {
    const unsigned idx = blockIdx.x * NTHREADS + threadIdx.x;

    // Decompose once (loop-invariant for q/oh/c; b changes by constant).
    unsigned q  = idx & (OW8 - 1);    // which 8-float chunk in the output row
    unsigned t  = idx >> 5;           // /OW8
    unsigned oh = t & (OH - 1);
    t >>= 8;                          // /OH
    unsigned c  = t & (C - 1);
    unsigned b  = t >> 6;             // /C

    unsigned h  = oh >> 1;
    unsigned j  = oh & 1;
    unsigned d0 = (j << 7) + c;       // (2j)*64 + c

    // float4 index of in[b][d0][h][4q]
    const unsigned i0 = (b * D + d0) * D_STRIDE_F4 + h * (W / 4) + q;

    // Phase 1: all 4 loads front-batched (MLP=4 LDG.128 per thread)
    float4 a0  = __ldg(&in[i0]);
    float4 b0  = __ldg(&in[i0 + D1_OFF_F4]);
    float4 a1  = __ldg(&in[i0 + I0_STEP_F4]);
    float4 b1  = __ldg(&in[i0 + I0_STEP_F4 + D1_OFF_F4]);

    // Phase 2: two 256-bit contiguous stores
    float* op = out + 8ull * idx;
    asm volatile(
        "st.global.v8.f32 [%0], {%1, %2, %3, %4, %5, %6, %7, %8};"
        :: "l"(op),
           "f"(a0.x), "f"(b0.x), "f"(a0.y), "f"(b0.y),
           "f"(a0.z), "f"(b0.z), "f"(a0.w), "f"(b0.w)
        : "memory");
    asm volatile(
        "st.global.v8.f32 [%0], {%1, %2, %3, %4, %5, %6, %7, %8};"
        :: "l"(op + OUT_STEP_F1),
           "f"(a1.x), "f"(b1.x), "f"(a1.y), "f"(b1.y),
           "f"(a1.z), "f"(b1.z), "f"(a1.w), "f"(b1.w)
        : "memory");
}

extern "C" void kernel_launch(void* const* d_in, const int* in_sizes, int n_in,
                              void* d_out, int out_size) {
    (void)in_sizes; (void)n_in; (void)out_size;
    const float4* in = (const float4*)d_in[0];
    float* out = (float*)d_out;
    d2s_kernel<<<NBLOCKS, NTHREADS>>>(in, out);
}

// round 9
// speedup vs baseline: 1.0254x; 1.0008x over previous
#include <cuda_runtime.h>
#include <cstdint>

// DepthToSpace (DCR, block=2): in [16,256,128,128] f32 -> out [16,64,256,256] f32
// out[b, c, 2h+j, 2w+r] = in[b, (2j+r)*64 + c, h, w]
//
// One thread handles two 8-float output chunks (idx and idx + 2^22). For a
// fixed output row, elements interleave two contiguous input rows
// d0 = 2j*64 + c and d1 = d0 + 64:
//   out[8q + 2k]   = in[d0][4q + k]
//   out[8q + 2k+1] = in[d1][4q + k]     k = 0..3
// => four coalesced 16B non-coherent loads (with L2::256B fetch-granularity
//    hint — pure streaming read, neighboring 128B line is always needed) +
//    two contiguous 32B stores (st.global.v8.f32, sm_100+).
// Warp footprints: 512B contiguous per LDG wavefront, 1024B contiguous fully
// written per STG wavefront.
//
// STRIDE = 2^22 touches only the b-field of the index decomposition, so the
// q/oh/c/h/j decomposition is computed once; the second chunk's addresses are
// compile-time-constant offsets.

static constexpr unsigned B  = 16;
static constexpr unsigned D  = 256;   // input channels
static constexpr unsigned C  = 64;    // output channels
static constexpr unsigned H  = 128;
static constexpr unsigned W  = 128;
static constexpr unsigned OH = 256;
static constexpr unsigned OW = 256;

static constexpr unsigned OW8 = OW / 8;                     // 32 chunks per out row
static constexpr unsigned TOTAL_F8 = B * C * OH * OW8;      // 8,388,608 chunks
static constexpr unsigned D_STRIDE_F4 = H * W / 4;          // 4096 float4 per input channel
static constexpr unsigned D1_OFF_F4   = C * D_STRIDE_F4;    // +64 channels, float4 units

static constexpr unsigned NBLOCKS  = 16384;
static constexpr unsigned NTHREADS = 256;
static constexpr unsigned STRIDE   = NBLOCKS * NTHREADS;    // 4,194,304 = 2^22
static constexpr unsigned NITERS   = TOTAL_F8 / STRIDE;     // exactly 2
static_assert(NITERS == 2, "layout assumes 2 chunks per thread");

// Between chunks only b increases by STRIDE / (OW8*OH*C) = 8:
static constexpr unsigned I0_STEP_F4  = 8u * D * D_STRIDE_F4;  // float4 units
static constexpr unsigned OUT_STEP_F1 = 8u * STRIDE;           // float units

__device__ __forceinline__ float4 ldg_nc_256(const float4* p) {
    float4 v;
    asm volatile("ld.global.nc.L2::256B.v4.f32 {%0, %1, %2, %3}, [%4];"
                 : "=f"(v.x), "=f"(v.y), "=f"(v.z), "=f"(v.w)
                 : "l"(p));
    return v;
}

__global__ void __launch_bounds__(NTHREADS) d2s_kernel(const float4* __restrict__ in,
                                                       float* __restrict__ out) {
    const unsigned idx = blockIdx.x * NTHREADS + threadIdx.x;

    // Decompose once (b-field change between chunks is a constant offset).
    unsigned q  = idx & (OW8 - 1);    // which 8-float chunk in the output row
    unsigned t  = idx >> 5;           // /OW8
    unsigned oh = t & (OH - 1);
    t >>= 8;                          // /OH
    unsigned c  = t & (C - 1);
    unsigned b  = t >> 6;             // /C

    unsigned h  = oh >> 1;
    unsigned j  = oh & 1;
    unsigned d0 = (j << 7) + c;       // (2j)*64 + c

    // float4 index of in[b][d0][h][4q]
    const unsigned i0 = (b * D + d0) * D_STRIDE_F4 + h * (W / 4) + q;

    // Phase 1: all 4 loads front-batched (MLP=4 LDG.128 per thread)
    float4 a0 = ldg_nc_256(&in[i0]);
    float4 b0 = ldg_nc_256(&in[i0 + D1_OFF_F4]);
    float4 a1 = ldg_nc_256(&in[i0 + I0_STEP_F4]);
    float4 b1 = ldg_nc_256(&in[i0 + I0_STEP_F4 + D1_OFF_F4]);

    // Phase 2: two 256-bit contiguous stores
    float* op = out + 8ull * idx;
    asm volatile(
        "st.global.v8.f32 [%0], {%1, %2, %3, %4, %5, %6, %7, %8};"
        :: "l"(op),
           "f"(a0.x), "f"(b0.x), "f"(a0.y), "f"(b0.y),
           "f"(a0.z), "f"(b0.z), "f"(a0.w), "f"(b0.w)
        : "memory");
    asm volatile(
        "st.global.v8.f32 [%0], {%1, %2, %3, %4, %5, %6, %7, %8};"
        :: "l"(op + OUT_STEP_F1),
           "f"(a1.x), "f"(b1.x), "f"(a1.y), "f"(b1.y),
           "f"(a1.z), "f"(b1.z), "f"(a1.w), "f"(b1.w)
        : "memory");
}

extern "C" void kernel_launch(void* const* d_in, const int* in_sizes, int n_in,
                              void* d_out, int out_size) {
    (void)in_sizes; (void)n_in; (void)out_size;
    const float4* in = (const float4*)d_in[0];
    float* out = (float*)d_out;
    d2s_kernel<<<NBLOCKS, NTHREADS>>>(in, out);
}

// round 10
// speedup vs baseline: 1.0274x; 1.0020x over previous
#include <cuda_runtime.h>
#include <cstdint>

// DepthToSpace (DCR, block=2): in [16,256,128,128] f32 -> out [16,64,256,256] f32
// out[b, c, 2h+j, 2w+r] = in[b, (2j+r)*64 + c, h, w]
//
// One thread per 8-float output chunk. For a fixed output row, elements
// interleave two contiguous input rows d0 = 2j*64 + c and d1 = d0 + 64:
//   out[8q + 2k]   = in[d0][4q + k]
//   out[8q + 2k+1] = in[d1][4q + k]     k = 0..3
// => two coalesced 16B non-coherent loads (L2::256B fetch hint — pure
//    streaming read, the neighboring 128B line is always needed) + ONE
//    contiguous 32B store (st.global.v8.f32, sm_100+).
// Warp footprints: 512B contiguous per LDG wavefront, 1024B contiguous fully
// written per STG wavefront. 32 B/thread output is the maximal fully-dense
// shape: any wider run forces lane-strided store wavefronts.
//
// 32768 CTAs x 1 chunk: minimal per-thread state (no loop), minimal regs,
// finest load-balancing quantum, MLP_p1=2 (lowest cross-CTA L1tex-queue
// spread per the B300 multi-CTA model).

static constexpr unsigned B  = 16;
static constexpr unsigned D  = 256;   // input channels
static constexpr unsigned C  = 64;    // output channels
static constexpr unsigned H  = 128;
static constexpr unsigned W  = 128;
static constexpr unsigned OH = 256;
static constexpr unsigned OW = 256;

static constexpr unsigned OW8 = OW / 8;                     // 32 chunks per out row
static constexpr unsigned TOTAL_F8 = B * C * OH * OW8;      // 8,388,608 chunks
static constexpr unsigned D_STRIDE_F4 = H * W / 4;          // 4096 float4 per input channel
static constexpr unsigned D1_OFF_F4   = C * D_STRIDE_F4;    // +64 channels, float4 units

static constexpr unsigned NTHREADS = 256;
static constexpr unsigned NBLOCKS  = TOTAL_F8 / NTHREADS;   // 32768

__device__ __forceinline__ float4 ldg_nc_256(const float4* p) {
    float4 v;
    asm volatile("ld.global.nc.L2::256B.v4.f32 {%0, %1, %2, %3}, [%4];"
                 : "=f"(v.x), "=f"(v.y), "=f"(v.z), "=f"(v.w)
                 : "l"(p));
    return v;
}

__global__ void __launch_bounds__(NTHREADS) d2s_kernel(const float4* __restrict__ in,
                                                       float* __restrict__ out) {
    const unsigned idx = blockIdx.x * NTHREADS + threadIdx.x;

    unsigned q  = idx & (OW8 - 1);    // which 8-float chunk in the output row
    unsigned t  = idx >> 5;           // /OW8
    unsigned oh = t & (OH - 1);
    t >>= 8;                          // /OH
    unsigned c  = t & (C - 1);
    unsigned b  = t >> 6;             // /C

    unsigned h  = oh >> 1;
    unsigned j  = oh & 1;
    unsigned d0 = (j << 7) + c;       // (2j)*64 + c

    // float4 index of in[b][d0][h][4q]
    const unsigned i0 = (b * D + d0) * D_STRIDE_F4 + h * (W / 4) + q;

    float4 a  = ldg_nc_256(&in[i0]);
    float4 bb = ldg_nc_256(&in[i0 + D1_OFF_F4]);

    // One 256-bit contiguous store: out floats [8*idx .. 8*idx+7].
    float* op = out + 8ull * idx;
    asm volatile(
        "st.global.v8.f32 [%0], {%1, %2, %3, %4, %5, %6, %7, %8};"
        :: "l"(op),
           "f"(a.x), "f"(bb.x), "f"(a.y), "f"(bb.y),
           "f"(a.z), "f"(bb.z), "f"(a.w), "f"(bb.w)
        : "memory");
}

extern "C" void kernel_launch(void* const* d_in, const int* in_sizes, int n_in,
                              void* d_out, int out_size) {
    (void)in_sizes; (void)n_in; (void)out_size;
    const float4* in = (const float4*)d_in[0];
    float* out = (float*)d_out;
    d2s_kernel<<<NBLOCKS, NTHREADS>>>(in, out);
}